// round 7
// baseline (speedup 1.0000x reference)
#include <cuda_runtime.h>

#define B_ 64
#define S_ 2048
#define I_ 128
#define H_ 512
#define O_ 128

// ---------------- scratch (device globals: no allocations allowed) ----------
__device__ float g_xin[(size_t)B_ * S_ * H_];   // input projection (B,S,H)
__device__ float g_hs [(size_t)B_ * S_ * H_];   // hidden states   (B,S,H)
__device__ float g_h[2][B_ * H_];               // double-buffered h ([b][k])
__device__ unsigned g_bar[32];                  // per batch-group barrier

// ---------------- helpers ----------------------------------------------------
__device__ __forceinline__ unsigned long long ffma2(unsigned long long a,
                                                    unsigned long long b,
                                                    unsigned long long c) {
    unsigned long long d;
    asm("fma.rn.f32x2 %0, %1, %2, %3;" : "=l"(d) : "l"(a), "l"(b), "l"(c));
    return d;
}
__device__ __forceinline__ unsigned long long pack2(float x, float y) {
    unsigned long long p;
    asm("mov.b64 %0, {%1, %2};" : "=l"(p) : "f"(x), "f"(y));
    return p;
}
__device__ __forceinline__ float2 unpack2(unsigned long long p) {
    float2 r;
    asm("mov.b64 {%0, %1}, %2;" : "=f"(r.x), "=f"(r.y) : "l"(p));
    return r;
}

// ---------------- init: reset barriers ---------------------------------------
__global__ void init_kernel() {
    if (threadIdx.x < 32) g_bar[threadIdx.x] = 0;
}

// ---------------- tiled fp32 GEMM:  C[M,N] = A[M,K] @ B[N,K]^T + bias --------
template <int N, int K, bool SRC_HS, bool DST_XIN>
__global__ __launch_bounds__(256) void gemm_kernel(const float* __restrict__ Ap,
                                                   const float* __restrict__ Bm,
                                                   const float* __restrict__ bias,
                                                   float* __restrict__ Cp) {
    __shared__ __align__(16) float Ast[32][132];
    __shared__ __align__(16) float Bst[32][132];
    const float* A = SRC_HS ? g_hs : Ap;
    float* C = DST_XIN ? g_xin : Cp;

    const int tid = threadIdx.x;
    const int bm = blockIdx.x, bn = blockIdx.y;
    const float* Ab = A + (size_t)bm * 128 * K;
    const float* Bb = Bm + (size_t)bn * 128 * K;

    const int tx = tid & 15, ty = tid >> 4;
    unsigned long long acc2[4][8];
#pragma unroll
    for (int i = 0; i < 4; i++)
#pragma unroll
        for (int j = 0; j < 8; j++) acc2[i][j] = 0ull;

    for (int k0 = 0; k0 < K; k0 += 32) {
#pragma unroll
        for (int u = 0; u < 4; u++) {
            int idx4 = tid + u * 256;
            int m = idx4 >> 3;
            int kq = (idx4 & 7) * 4;
            float4 va = *(const float4*)&Ab[(size_t)m * K + k0 + kq];
            Ast[kq + 0][m] = va.x; Ast[kq + 1][m] = va.y;
            Ast[kq + 2][m] = va.z; Ast[kq + 3][m] = va.w;
            float4 vb = *(const float4*)&Bb[(size_t)m * K + k0 + kq];
            Bst[kq + 0][m] = vb.x; Bst[kq + 1][m] = vb.y;
            Bst[kq + 2][m] = vb.z; Bst[kq + 3][m] = vb.w;
        }
        __syncthreads();
#pragma unroll
        for (int kc = 0; kc < 32; kc++) {
            float4 a0 = *(const float4*)&Ast[kc][ty * 8];
            float4 a1 = *(const float4*)&Ast[kc][ty * 8 + 4];
            float4 b0 = *(const float4*)&Bst[kc][tx * 8];
            float4 b1 = *(const float4*)&Bst[kc][tx * 8 + 4];
            unsigned long long A2[4] = {pack2(a0.x, a0.y), pack2(a0.z, a0.w),
                                        pack2(a1.x, a1.y), pack2(a1.z, a1.w)};
            float bb[8] = {b0.x, b0.y, b0.z, b0.w, b1.x, b1.y, b1.z, b1.w};
#pragma unroll
            for (int j = 0; j < 8; j++) {
                unsigned long long B2 = pack2(bb[j], bb[j]);
#pragma unroll
                for (int i = 0; i < 4; i++) acc2[i][j] = ffma2(A2[i], B2, acc2[i][j]);
            }
        }
        __syncthreads();
    }
#pragma unroll
    for (int i = 0; i < 4; i++) {
        size_t m0 = (size_t)bm * 128 + ty * 8 + 2 * i;
#pragma unroll
        for (int j = 0; j < 8; j++) {
            int n = bn * 128 + tx * 8 + j;
            float2 v = unpack2(acc2[i][j]);
            C[m0 * N + n]       = v.x + bias[n];
            C[(m0 + 1) * N + n] = v.y + bias[n];
        }
    }
}

// ---------------- recurrent scan ---------------------------------------------
// 128 CTAs = 32 batch-groups (2 batches) x 4 output-slices (128 cols).
// Lane (jo=lane>>3, kg=lane&7): K-slice kg*64; outputs j0 = ng*128+w*8+jo*2,
// j1 = j0+1 (2 j per lane, W = 64 regs). Reduce over kg via shfl.bfly.
// h in smem, permuted+swizzled float4 slots: quad kq -> (kq&15)*8+((kq>>4)^(kq&7))
// -> both staging stores and compute reads are conflict-free 128B wavefronts.
// Exchange via L2 double buffer + 4-CTA monotonic atomic barrier (R1-proven).
__global__ __launch_bounds__(512, 1) void scan_kernel(const float* __restrict__ h0,
                                                      const float* __restrict__ Wrec,
                                                      float* __restrict__ hfinal) {
    __shared__ __align__(16) float h_s[2 * H_];     // 4 KB, permuted layout

    const int tid = threadIdx.x;
    const int bg = blockIdx.x >> 2;                 // batch-group 0..31 (2 b)
    const int ng = blockIdx.x & 3;                  // output slice 0..3
    const int w = tid >> 5, lane = tid & 31;
    const int kg = lane & 7;                        // K-slice 0..7 (64-wide)
    const int jo = lane >> 3;                       // 0..3
    const int j0 = ng * 128 + w * 8 + jo * 2;       // first of 2 output cols

    // ---- W_rec[j0][kg*64..] and W_rec[j0+1][kg*64..], k-pair packed
    unsigned long long Wr0[32], Wr1[32];
    {
        const float4* wp0 = (const float4*)&Wrec[(size_t)j0 * H_ + kg * 64];
        const float4* wp1 = (const float4*)&Wrec[(size_t)(j0 + 1) * H_ + kg * 64];
#pragma unroll
        for (int q = 0; q < 16; q++) {
            float4 v0 = wp0[q];
            Wr0[2 * q] = pack2(v0.x, v0.y);  Wr0[2 * q + 1] = pack2(v0.z, v0.w);
            float4 v1 = wp1[q];
            Wr1[2 * q] = pack2(v1.x, v1.y);  Wr1[2 * q + 1] = pack2(v1.z, v1.w);
        }
    }

    // ---- staging identity (first 256 threads): b = tid>>7, quad kq = tid&127
    const int rb = (tid >> 7) & 1;
    const int rkq = tid & 127;
    const int rslot = (rkq & 15) * 8 + (((rkq >> 4) ^ rkq) & 7);
    const size_t rsrc_off = (size_t)(bg * 2 + rb) * H_ + rkq * 4;

    const ulonglong2* h2 = (const ulonglong2*)h_s;

    // ---- preamble: h0 -> smem (permuted), xin t=0 for writer lanes
    if (tid < 256)
        *(float4*)&h_s[(rb * 128 + rslot) * 4] = *(const float4*)&h0[rsrc_off];
    __syncthreads();

    const bool writer = (kg < 2);                   // b = kg for writers
    float2 xr = make_float2(0.f, 0.f);
    if (writer)
        xr = *(const float2*)&g_xin[((size_t)(bg * 2 + kg) * S_) * H_ + j0];

    for (int t = 0; t < S_; t++) {
        const int nxt = (t + 1) & 1;

        // ---- prefetch xin(t+1) on writer lanes (hidden under compute)
        float2 xn = make_float2(0.f, 0.f);
        if (writer && t + 1 < S_)
            xn = *(const float2*)&g_xin[((size_t)(bg * 2 + kg) * S_ + (t + 1)) * H_ + j0];

        // ---- partial GEMM: 16 quads x 2 batches x 2 j (f32x2)
        unsigned long long a00 = 0, a01 = 0, a10 = 0, a11 = 0;  // [jj][b]
#pragma unroll
        for (int q = 0; q < 16; q++) {
            const int sl = q * 8 + (kg ^ (q & 7));
            ulonglong2 u0 = h2[sl];            // b=0
            a00 = ffma2(Wr0[2 * q], u0.x, a00);
            a00 = ffma2(Wr0[2 * q + 1], u0.y, a00);
            a10 = ffma2(Wr1[2 * q], u0.x, a10);
            a10 = ffma2(Wr1[2 * q + 1], u0.y, a10);
            ulonglong2 u1 = h2[128 + sl];      // b=1
            a01 = ffma2(Wr0[2 * q], u1.x, a01);
            a01 = ffma2(Wr0[2 * q + 1], u1.y, a01);
            a11 = ffma2(Wr1[2 * q], u1.x, a11);
            a11 = ffma2(Wr1[2 * q + 1], u1.y, a11);
        }
        float2 f00 = unpack2(a00), f01 = unpack2(a01);
        float2 f10 = unpack2(a10), f11 = unpack2(a11);
        float s00 = f00.x + f00.y, s01 = f01.x + f01.y;
        float s10 = f10.x + f10.y, s11 = f11.x + f11.y;

        // ---- reduce over the 8 kg lanes
#pragma unroll
        for (int m = 1; m < 8; m <<= 1) {
            s00 += __shfl_xor_sync(0xFFFFFFFF, s00, m);
            s01 += __shfl_xor_sync(0xFFFFFFFF, s01, m);
            s10 += __shfl_xor_sync(0xFFFFFFFF, s10, m);
            s11 += __shfl_xor_sync(0xFFFFFFFF, s11, m);
        }

        // ---- finalize on writer lanes only (kg<2 -> b=kg): 2 tanh each
        if (writer) {
            const float sj0 = (kg == 0) ? s00 : s01;   // j0, b=kg
            const float sj1 = (kg == 0) ? s10 : s11;   // j1, b=kg
            float2 hv;
            hv.x = tanhf(sj0 + xr.x);
            hv.y = tanhf(sj1 + xr.y);
            const int bglob = bg * 2 + kg;
            *(float2*)&g_hs[((size_t)bglob * S_ + t) * H_ + j0] = hv;
            if (t + 1 < S_) *(float2*)&g_h[nxt][(size_t)bglob * H_ + j0] = hv;
            else            *(float2*)&hfinal[(size_t)bglob * H_ + j0] = hv;
            xr = xn;
        }

        if (t + 1 == S_) break;

        __syncthreads();   // all writers' STGs issued before elected fence

        // ---- per-batch-group barrier (4 CTAs), monotonic counter
        if (tid == 0) {
            __threadfence();
            atomicAdd(&g_bar[bg], 1u);
            unsigned tgt = 4u * (unsigned)(t + 1);
            while (*(volatile unsigned*)&g_bar[bg] < tgt) { }
            __threadfence();
        }
        __syncthreads();

        // ---- reload h(t+1) (4 KB) from L2 into permuted smem
        if (tid < 256)
            *(float4*)&h_s[(rb * 128 + rslot) * 4] =
                *(const float4*)&g_h[nxt][rsrc_off];
        __syncthreads();
    }
}

// ---------------- launch ------------------------------------------------------
extern "C" void kernel_launch(void* const* d_in, const int* in_sizes, int n_in,
                              void* d_out, int out_size) {
    const float* inputs  = (const float*)d_in[0];
    const float* h0      = (const float*)d_in[1];
    const float* W_in_w  = (const float*)d_in[2];
    const float* W_in_b  = (const float*)d_in[3];
    const float* W_rec_w = (const float*)d_in[4];
    const float* W_out_w = (const float*)d_in[5];
    const float* W_out_b = (const float*)d_in[6];

    float* out    = (float*)d_out;                      // (B,S,O)
    float* hfinal = out + (size_t)B_ * S_ * O_;         // (B,H)

    // 1) xin = inputs @ W_in^T + b   -> g_xin
    {
        dim3 grid(B_ * S_ / 128, H_ / 128);
        gemm_kernel<H_, I_, false, true><<<grid, 256>>>(inputs, W_in_w, W_in_b, nullptr);
    }
    // 2) barrier reset
    init_kernel<<<1, 32>>>();

    // 3) sequential scan: 128 co-resident CTAs, L2 exchange, 4-CTA groups
    scan_kernel<<<128, 512>>>(h0, W_rec_w, hfinal);

    // 4) outputs = hs @ W_out^T + b  -> d_out
    {
        dim3 grid(B_ * S_ / 128, O_ / 128);
        gemm_kernel<O_, H_, true, false><<<grid, 256>>>(nullptr, W_out_w, W_out_b, out);
    }
}

// round 8
// speedup vs baseline: 1.0432x; 1.0432x over previous
#include <cuda_runtime.h>

#define B_ 64
#define S_ 2048
#define I_ 128
#define H_ 512
#define O_ 128

// ---------------- scratch (device globals: no allocations allowed) ----------
__device__ float g_hs [(size_t)B_ * S_ * H_];   // hidden states (B,S,H)
__device__ float g_h[2][B_ * H_];               // double-buffered h ([b][k])
__device__ unsigned g_bar[16];                  // per batch-group barrier

// ---------------- helpers ----------------------------------------------------
__device__ __forceinline__ unsigned long long ffma2(unsigned long long a,
                                                    unsigned long long b,
                                                    unsigned long long c) {
    unsigned long long d;
    asm("fma.rn.f32x2 %0, %1, %2, %3;" : "=l"(d) : "l"(a), "l"(b), "l"(c));
    return d;
}
__device__ __forceinline__ unsigned long long pack2(float x, float y) {
    unsigned long long p;
    asm("mov.b64 %0, {%1, %2};" : "=l"(p) : "f"(x), "f"(y));
    return p;
}
__device__ __forceinline__ float2 unpack2(unsigned long long p) {
    float2 r;
    asm("mov.b64 {%0, %1}, %2;" : "=f"(r.x), "=f"(r.y) : "l"(p));
    return r;
}
__device__ __forceinline__ float tanh_approx(float x) {
    float r;
    asm("tanh.approx.f32 %0, %1;" : "=f"(r) : "f"(x));
    return r;
}

// ---------------- init: reset barriers ---------------------------------------
__global__ void init_kernel() {
    if (threadIdx.x < 16) g_bar[threadIdx.x] = 0;
}

// ---------------- output GEMM:  C[M,128] = hs[M,512] @ W_out[128,512]^T + b --
__global__ __launch_bounds__(256) void gemm_out_kernel(const float* __restrict__ Bm,
                                                       const float* __restrict__ bias,
                                                       float* __restrict__ C) {
    __shared__ __align__(16) float Ast[32][132];
    __shared__ __align__(16) float Bst[32][132];
    const int tid = threadIdx.x;
    const int bm = blockIdx.x;
    const float* Ab = g_hs + (size_t)bm * 128 * H_;

    const int tx = tid & 15, ty = tid >> 4;
    unsigned long long acc2[4][8];
#pragma unroll
    for (int i = 0; i < 4; i++)
#pragma unroll
        for (int j = 0; j < 8; j++) acc2[i][j] = 0ull;

    for (int k0 = 0; k0 < H_; k0 += 32) {
#pragma unroll
        for (int u = 0; u < 4; u++) {
            int idx4 = tid + u * 256;
            int m = idx4 >> 3;
            int kq = (idx4 & 7) * 4;
            float4 va = *(const float4*)&Ab[(size_t)m * H_ + k0 + kq];
            Ast[kq + 0][m] = va.x; Ast[kq + 1][m] = va.y;
            Ast[kq + 2][m] = va.z; Ast[kq + 3][m] = va.w;
            float4 vb = *(const float4*)&Bm[(size_t)m * H_ + k0 + kq];
            Bst[kq + 0][m] = vb.x; Bst[kq + 1][m] = vb.y;
            Bst[kq + 2][m] = vb.z; Bst[kq + 3][m] = vb.w;
        }
        __syncthreads();
#pragma unroll
        for (int kc = 0; kc < 32; kc++) {
            float4 a0 = *(const float4*)&Ast[kc][ty * 8];
            float4 a1 = *(const float4*)&Ast[kc][ty * 8 + 4];
            float4 b0 = *(const float4*)&Bst[kc][tx * 8];
            float4 b1 = *(const float4*)&Bst[kc][tx * 8 + 4];
            unsigned long long A2[4] = {pack2(a0.x, a0.y), pack2(a0.z, a0.w),
                                        pack2(a1.x, a1.y), pack2(a1.z, a1.w)};
            float bb[8] = {b0.x, b0.y, b0.z, b0.w, b1.x, b1.y, b1.z, b1.w};
#pragma unroll
            for (int j = 0; j < 8; j++) {
                unsigned long long B2 = pack2(bb[j], bb[j]);
#pragma unroll
                for (int i = 0; i < 4; i++) acc2[i][j] = ffma2(A2[i], B2, acc2[i][j]);
            }
        }
        __syncthreads();
    }
#pragma unroll
    for (int i = 0; i < 4; i++) {
        size_t m0 = (size_t)bm * 128 + ty * 8 + 2 * i;
#pragma unroll
        for (int j = 0; j < 8; j++) {
            int n = tx * 8 + j;
            float2 v = unpack2(acc2[i][j]);
            C[m0 * O_ + n]       = v.x + bias[n];
            C[(m0 + 1) * O_ + n] = v.y + bias[n];
        }
    }
}

// ---------------- recurrent scan (fused input projection) --------------------
// 128 CTAs = 16 batch-groups (4 batches) x 8 output-slices (64 cols).
// Lane (jo=lane>>3, kg=lane&7): output j = ng*64 + w*4 + jo (1 j per lane);
// K-slice = h[kg*64..+63] PLUS x[kg*16..+15] (input projection fused).
// h in smem, permuted/swizzled float4 slots (proven in R6):
//   quad kq -> slot (kq&15)*8 + ((kq>>4)^(kq&7)); reads sl = q*8 + (kg^(q&7)).
// x_t in smem, double-buffered, chunk(iq) = (iq&3)*8 + (iq>>2) (conflict-free).
// Reduce over 8 kg lanes via shfl.bfly; writers (kg<4 -> b=kg) do 1 tanh each.
// Exchange: L2 double buffer + R1's proven monotonic atomic barrier.
__global__ __launch_bounds__(512, 1) void scan_kernel(const float* __restrict__ h0,
                                                      const float* __restrict__ Wrec,
                                                      const float* __restrict__ Win,
                                                      const float* __restrict__ Winb,
                                                      const float* __restrict__ inputs,
                                                      float* __restrict__ hfinal) {
    __shared__ __align__(16) float h_s[4 * H_];       // 8 KB, permuted
    __shared__ __align__(16) float x_s[2][4][128];    // 4 KB, double-buffered

    const int tid = threadIdx.x;
    const int bg = blockIdx.x >> 3;                 // batch-group 0..15
    const int ng = blockIdx.x & 7;                  // output slice 0..7
    const int w = tid >> 5, lane = tid & 31;
    const int kg = lane & 7;                        // K-slice 0..7
    const int jo = lane >> 3;                       // 0..3
    const int jg = ng * 64 + w * 4 + jo;            // this lane's output col

    // ---- W_rec[jg][kg*64..+63] (32 ull) + W_in[jg][kg*16..+15] (8 ull)
    unsigned long long Wr[32], Wi[8];
    {
        const float4* wp = (const float4*)&Wrec[(size_t)jg * H_ + kg * 64];
#pragma unroll
        for (int q = 0; q < 16; q++) {
            float4 v = wp[q];
            Wr[2 * q]     = pack2(v.x, v.y);
            Wr[2 * q + 1] = pack2(v.z, v.w);
        }
        const float4* ip = (const float4*)&Win[(size_t)jg * I_ + kg * 16];
#pragma unroll
        for (int q = 0; q < 4; q++) {
            float4 v = ip[q];
            Wi[2 * q]     = pack2(v.x, v.y);
            Wi[2 * q + 1] = pack2(v.z, v.w);
        }
    }
    const float bias = Winb[jg];

    // ---- h staging identity: b = tid>>7, quad kq = tid&127 (all 512 thr)
    const int rb = tid >> 7;
    const int rkq = tid & 127;
    const int rslot = (rkq & 15) * 8 + (((rkq >> 4) ^ rkq) & 7);
    const size_t rsrc_off = (size_t)(bg * 4 + rb) * H_ + rkq * 4;

    // ---- x staging identity (first 128 threads): sb = tid>>5, il = tid&31
    const int sb = (tid >> 5) & 3;
    const int il = tid & 31;
    const int sphys = (il & 3) * 8 + (il >> 2);     // chunk within x_s[.][sb]
    const bool xstager = (tid < 128);

    const ulonglong2* h2 = (const ulonglong2*)h_s;

    // ---- preamble: h0 + x(0) -> smem
    *(float4*)&h_s[(rb * 128 + rslot) * 4] = *(const float4*)&h0[rsrc_off];
    if (xstager) {
        float4 xv = *(const float4*)&inputs[((size_t)(bg * 4 + sb) * S_) * I_ + il * 4];
        *(float4*)&x_s[0][sb][sphys * 4] = xv;
    }
    __syncthreads();

    const bool writer = (kg < 4);                   // b = kg

    for (int t = 0; t < S_; t++) {
        const int cur = t & 1, nxt = cur ^ 1;

        // ---- issue x(t+1) LDG early (DRAM latency hidden under compute)
        float4 xload;
        const bool do_x = xstager && (t + 1 < S_);
        if (do_x)
            xload = *(const float4*)&inputs[((size_t)(bg * 4 + sb) * S_ + (t + 1)) * I_ + il * 4];

        // ---- partial GEMM: h (16 quads) + x (4 quads), 4 batches, f32x2
        unsigned long long a0 = 0, a1 = 0, a2 = 0, a3 = 0;
#pragma unroll
        for (int q = 0; q < 16; q++) {
            const int sl = q * 8 + (kg ^ (q & 7));
            ulonglong2 u0 = h2[sl];
            a0 = ffma2(Wr[2 * q], u0.x, a0);
            a0 = ffma2(Wr[2 * q + 1], u0.y, a0);
            ulonglong2 u1 = h2[128 + sl];
            a1 = ffma2(Wr[2 * q], u1.x, a1);
            a1 = ffma2(Wr[2 * q + 1], u1.y, a1);
            ulonglong2 u2 = h2[256 + sl];
            a2 = ffma2(Wr[2 * q], u2.x, a2);
            a2 = ffma2(Wr[2 * q + 1], u2.y, a2);
            ulonglong2 u3 = h2[384 + sl];
            a3 = ffma2(Wr[2 * q], u3.x, a3);
            a3 = ffma2(Wr[2 * q + 1], u3.y, a3);
        }
#pragma unroll
        for (int q = 0; q < 4; q++) {
            const int xc = (q * 8 + kg) * 4;        // float index within x_s[.][b]
            ulonglong2 x0 = *(const ulonglong2*)&x_s[cur][0][xc];
            a0 = ffma2(Wi[2 * q], x0.x, a0);
            a0 = ffma2(Wi[2 * q + 1], x0.y, a0);
            ulonglong2 x1 = *(const ulonglong2*)&x_s[cur][1][xc];
            a1 = ffma2(Wi[2 * q], x1.x, a1);
            a1 = ffma2(Wi[2 * q + 1], x1.y, a1);
            ulonglong2 x2 = *(const ulonglong2*)&x_s[cur][2][xc];
            a2 = ffma2(Wi[2 * q], x2.x, a2);
            a2 = ffma2(Wi[2 * q + 1], x2.y, a2);
            ulonglong2 x3 = *(const ulonglong2*)&x_s[cur][3][xc];
            a3 = ffma2(Wi[2 * q], x3.x, a3);
            a3 = ffma2(Wi[2 * q + 1], x3.y, a3);
        }
        float2 f0 = unpack2(a0), f1 = unpack2(a1), f2 = unpack2(a2), f3 = unpack2(a3);
        float s0 = f0.x + f0.y, s1 = f1.x + f1.y, s2 = f2.x + f2.y, s3 = f3.x + f3.y;

        // ---- reduce over the 8 kg lanes
#pragma unroll
        for (int m = 1; m < 8; m <<= 1) {
            s0 += __shfl_xor_sync(0xFFFFFFFF, s0, m);
            s1 += __shfl_xor_sync(0xFFFFFFFF, s1, m);
            s2 += __shfl_xor_sync(0xFFFFFFFF, s2, m);
            s3 += __shfl_xor_sync(0xFFFFFFFF, s3, m);
        }

        // ---- stage x(t+1) into smem (ready after the post-barrier sync)
        if (do_x)
            *(float4*)&x_s[nxt][sb][sphys * 4] = xload;

        // ---- finalize on writer lanes: 1 tanh each, publish to L2
        float hv = 0.f;
        if (writer) {
            float sv = (kg == 0) ? s0 : (kg == 1) ? s1 : (kg == 2) ? s2 : s3;
            hv = tanh_approx(sv + bias);
            const int bglob = bg * 4 + kg;
            if (t + 1 < S_) g_h[nxt][(size_t)bglob * H_ + jg] = hv;
            else            hfinal[(size_t)bglob * H_ + jg] = hv;
        }
        __syncthreads();   // writer STGs issued before elected release

        // ---- history write (off the critical inter-CTA chain)
        if (writer)
            g_hs[((size_t)(bg * 4 + kg) * S_ + t) * H_ + jg] = hv;

        if (t + 1 == S_) break;

        // ---- per-batch-group barrier (8 CTAs), R1-proven monotonic counter
        if (tid == 0) {
            __threadfence();
            atomicAdd(&g_bar[bg], 1u);
            unsigned tgt = 8u * (unsigned)(t + 1);
            while (*(volatile unsigned*)&g_bar[bg] < tgt) { }
            __threadfence();
        }
        __syncthreads();

        // ---- reload h(t+1) (8 KB) from L2 into permuted smem
        *(float4*)&h_s[(rb * 128 + rslot) * 4] =
            *(const float4*)&g_h[nxt][rsrc_off];
        __syncthreads();
    }
}

// ---------------- launch ------------------------------------------------------
extern "C" void kernel_launch(void* const* d_in, const int* in_sizes, int n_in,
                              void* d_out, int out_size) {
    const float* inputs  = (const float*)d_in[0];
    const float* h0      = (const float*)d_in[1];
    const float* W_in_w  = (const float*)d_in[2];
    const float* W_in_b  = (const float*)d_in[3];
    const float* W_rec_w = (const float*)d_in[4];
    const float* W_out_w = (const float*)d_in[5];
    const float* W_out_b = (const float*)d_in[6];

    float* out    = (float*)d_out;                      // (B,S,O)
    float* hfinal = out + (size_t)B_ * S_ * O_;         // (B,H)

    // 1) barrier reset
    init_kernel<<<1, 32>>>();

    // 2) fused scan (input projection computed in-kernel; no pre-GEMM)
    scan_kernel<<<128, 512>>>(h0, W_rec_w, W_in_w, W_in_b, inputs, hfinal);

    // 3) outputs = hs @ W_out^T + b  -> d_out
    gemm_out_kernel<<<B_ * S_ / 128, 256>>>(W_out_w, W_out_b, out);
}